// round 7
// baseline (speedup 1.0000x reference)
#include <cuda_runtime.h>
#include <cstdint>

// QNADE — autoregressive NADE. N=8192, D=64, H=4096, M=2.
// acc holds PRE-SCALED pre-activation: acc' = 2*log2(e) * (b1 + sum x_j W1[j]).
// Per step: q = 1/(exp2(acc')+1) via 4-way shared rcp; dot q vs W2;
// z = C - 2*dot; leader does accurate tanh/normalize/select.

#define N_SAMP   8192
#define D_SITES  64
#define H_DIM    4096
#define B_SAMP   4            // samples per CTA (2 groups x 2 samples/thread)
#define THREADS  512
#define HPART    256          // threads per sample-group
#define PER_THR  16           // h-elements per thread
#define PAD_CH   20           // 16 data + 4 pad words; stride%32==20 -> LDS.128 conflict-free
#define W1_FLOATS (HPART * PAD_CH)   // 5120
#define KTANH    2.8853900817779268f // 2*log2(e)

typedef unsigned long long ull;

__device__ __forceinline__ ull pk(float a, float b) {
    ull r; asm("mov.b64 %0, {%1, %2};" : "=l"(r) : "f"(a), "f"(b)); return r;
}
__device__ __forceinline__ void upk(ull v, float& a, float& b) {
    asm("mov.b64 {%0, %1}, %2;" : "=f"(a), "=f"(b) : "l"(v));
}
__device__ __forceinline__ ull fma2(ull a, ull b, ull c) {
    ull d; asm("fma.rn.f32x2 %0, %1, %2, %3;" : "=l"(d) : "l"(a), "l"(b), "l"(c)); return d;
}
__device__ __forceinline__ float fex2(float x) {
    float e; asm("ex2.approx.f32 %0, %1;" : "=f"(e) : "f"(x)); return e;
}
__device__ __forceinline__ float frcp(float x) {
    float r; asm("rcp.approx.f32 %0, %1;" : "=f"(r) : "f"(x)); return r;
}
__device__ __forceinline__ void cp16(uint32_t dst, const void* src) {
    asm volatile("cp.async.ca.shared.global [%0], [%1], 16;" :: "r"(dst), "l"(src));
}

// 4 elements of one sample: q_i = 1/(exp2(acc_i)+1), dot into d0v/d1v, acc update.
// One rcp shared across 4 via prefix-suffix products.
__device__ __forceinline__ void process4(ull& a0, ull& a1,
                                         ull w1x, ull w1y,
                                         ull wxx, ull wxy,
                                         ull wyx, ull wyy,
                                         ull xv, ull& d0v, ull& d1v) {
    float s0, s1, s2, s3;
    upk(a0, s0, s1); upk(a1, s2, s3);
    const float e0 = fex2(s0), e1 = fex2(s1), e2 = fex2(s2), e3 = fex2(s3);
    const float u0 = e0 + 1.0f, u1 = e1 + 1.0f, u2 = e2 + 1.0f, u3 = e3 + 1.0f;
    const float b = u0 * u1;
    const float c = b * u2;
    const float p = c * u3;
    const float r  = frcp(p);
    const float q3 = r * c;
    const float r3 = r * u3;
    const float q2 = r3 * b;
    const float r2 = r3 * u2;          // = 1/(u0*u1)
    const float q1 = r2 * u0;
    const float q0 = r2 * u1;
    const ull qv0 = pk(q0, q1);
    const ull qv1 = pk(q2, q3);
    d0v = fma2(qv0, wxx, d0v);  d0v = fma2(qv1, wxy, d0v);
    d1v = fma2(qv0, wyx, d1v);  d1v = fma2(qv1, wyy, d1v);
    a0 = fma2(xv, w1x, a0);
    a1 = fma2(xv, w1y, a1);
}

__global__ __launch_bounds__(THREADS, 2)
void qnade_kernel(const float* __restrict__ x,
                  const float* __restrict__ W1,
                  const float* __restrict__ b1,
                  const float* __restrict__ W2,
                  const float* __restrict__ b2,
                  float* __restrict__ out)
{
    // smem (floats): W1s[2][5120] | W2xs[5120] | W2ys[5120] | Xs[256] | red[2][16] float4
    extern __shared__ float smem[];
    float*  W1s  = smem;
    float*  W2xs = smem + 2 * W1_FLOATS;
    float*  W2ys = W2xs + W1_FLOATS;
    float*  Xs   = W2ys + W1_FLOATS;
    float4* red  = (float4*)(Xs + B_SAMP * D_SITES);

    const int t    = threadIdx.x;
    const int hp   = t & 255;       // h-chunk 0..255 (16 h-values each)
    const int grp  = t >> 8;        // sample group 0/1 -> samples {2g, 2g+1}
    const int warp = t >> 5;
    const int lane = t & 31;
    const int n0   = blockIdx.x * B_SAMP;
    const bool leader = (hp == 0);
    const uint32_t smem_u32 = (uint32_t)__cvta_generic_to_shared(smem);

    // ---- stage W2 (split, padded chunks), spins, W1 row 0 ----
    const float2* W2g = (const float2*)W2;
    #pragma unroll
    for (int i = t; i < H_DIM; i += THREADS) {
        const float2 g = W2g[i];
        const int c = i >> 4, k = i & 15;
        W2xs[c * PAD_CH + k] = g.x;
        W2ys[c * PAD_CH + k] = g.y;
    }
    if (t < B_SAMP * D_SITES)
        Xs[t] = x[(size_t)n0 * D_SITES + t];
    #pragma unroll
    for (int j = t; j < H_DIM / 4; j += THREADS)
        cp16(smem_u32 + (uint32_t)((j >> 2) * PAD_CH + ((j & 3) << 2)) * 4u, W1 + 4 * j);
    asm volatile("cp.async.commit_group;");

    // ---- acc init: pre-scaled b1, both samples identical ----
    ull acc[2][8];
    {
        const float4* b1v = (const float4*)(b1 + hp * PER_THR);
        #pragma unroll
        for (int k = 0; k < 4; k++) {
            const float4 v = b1v[k];
            const ull lo = pk(KTANH * v.x, KTANH * v.y);
            const ull hi = pk(KTANH * v.z, KTANH * v.w);
            acc[0][2 * k] = lo; acc[0][2 * k + 1] = hi;
            acc[1][2 * k] = lo; acc[1][2 * k + 1] = hi;
        }
    }

    asm volatile("cp.async.wait_group 0;" ::: "memory");
    __syncthreads();   // W2/Xs/W1row0 visible

    // ---- one-time C0/C1 = sum(W2col) + b2 (uses red[1]; step 0 uses red[0]) ----
    float C0 = 0.0f, C1 = 0.0f;
    {
        float sx = 0.0f, sy = 0.0f;
        const float4* wx4 = (const float4*)(W2xs + hp * PAD_CH);
        const float4* wy4 = (const float4*)(W2ys + hp * PAD_CH);
        #pragma unroll
        for (int k = 0; k < 4; k++) {
            const float4 a = wx4[k], bq = wy4[k];
            sx += (a.x + a.y) + (a.z + a.w);
            sy += (bq.x + bq.y) + (bq.z + bq.w);
        }
        #pragma unroll
        for (int o = 16; o; o >>= 1) {
            sx += __shfl_xor_sync(0xffffffffu, sx, o);
            sy += __shfl_xor_sync(0xffffffffu, sy, o);
        }
        if (lane == 0) red[16 + warp] = make_float4(sx, sy, 0.0f, 0.0f);
        __syncthreads();
        if (leader) {
            float a0s = 0.0f, a1s = 0.0f;
            #pragma unroll
            for (int w = 0; w < 8; w++) {
                const float4 v = red[16 + grp * 8 + w];
                a0s += v.x; a1s += v.y;
            }
            C0 = a0s + b2[0];
            C1 = a1s + b2[1];
        }
    }

    const int sl0 = grp * 2, sl1 = grp * 2 + 1;
    float wav0 = 1.0f, wav1 = 1.0f;
    int buf = 0;

    const float* WXb = W2xs + hp * PAD_CH;
    const float* WYb = W2ys + hp * PAD_CH;

    for (int d = 0; d < D_SITES; d++) {
        // prefetch W1 row d+1 into other buffer
        if (d + 1 < D_SITES) {
            const float* src = W1 + (size_t)(d + 1) * H_DIM;
            const uint32_t dbase = smem_u32 + (uint32_t)((buf ^ 1) * W1_FLOATS) * 4u;
            #pragma unroll
            for (int j = t; j < H_DIM / 4; j += THREADS)
                cp16(dbase + (uint32_t)((j >> 2) * PAD_CH + ((j & 3) << 2)) * 4u, src + 4 * j);
        }
        asm volatile("cp.async.commit_group;");

        const float xs0 = Xs[sl0 * D_SITES + d];
        const float xs1 = Xs[sl1 * D_SITES + d];
        const float cx0 = KTANH * xs0, cx1 = KTANH * xs1;
        const ull xv0 = pk(cx0, cx0);
        const ull xv1 = pk(cx1, cx1);

        const float* W1b = W1s + buf * W1_FLOATS + hp * PAD_CH;
        ull d0v0 = 0ull, d1v0 = 0ull, d0v1 = 0ull, d1v1 = 0ull;

        #pragma unroll
        for (int q = 0; q < 4; q++) {
            const ulonglong2 w1q = *(const ulonglong2*)(W1b + 4 * q);
            const ulonglong2 wxq = *(const ulonglong2*)(WXb + 4 * q);
            const ulonglong2 wyq = *(const ulonglong2*)(WYb + 4 * q);
            process4(acc[0][2 * q], acc[0][2 * q + 1],
                     w1q.x, w1q.y, wxq.x, wxq.y, wyq.x, wyq.y, xv0, d0v0, d1v0);
            process4(acc[1][2 * q], acc[1][2 * q + 1],
                     w1q.x, w1q.y, wxq.x, wxq.y, wyq.x, wyq.y, xv1, d0v1, d1v1);
        }

        float a, b;
        upk(d0v0, a, b); float D00 = a + b;
        upk(d1v0, a, b); float D10 = a + b;
        upk(d0v1, a, b); float D01 = a + b;
        upk(d1v1, a, b); float D11 = a + b;

        #pragma unroll
        for (int o = 16; o; o >>= 1) {
            D00 += __shfl_xor_sync(0xffffffffu, D00, o);
            D10 += __shfl_xor_sync(0xffffffffu, D10, o);
            D01 += __shfl_xor_sync(0xffffffffu, D01, o);
            D11 += __shfl_xor_sync(0xffffffffu, D11, o);
        }
        if (lane == 0) red[(d & 1) * 16 + warp] = make_float4(D00, D10, D01, D11);

        asm volatile("cp.async.wait_group 0;" ::: "memory");
        __syncthreads();   // publishes red AND next W1 buffer

        if (leader) {
            float S00 = 0.0f, S10 = 0.0f, S01 = 0.0f, S11 = 0.0f;
            #pragma unroll
            for (int w = 0; w < 8; w++) {
                const float4 v = red[(d & 1) * 16 + grp * 8 + w];
                S00 += v.x; S10 += v.y; S01 += v.z; S11 += v.w;
            }
            // sample 0 of this group
            {
                const float z0 = fmaf(-2.0f, S00, C0);
                const float z1 = fmaf(-2.0f, S10, C1);
                const float t0 = tanhf(z0), t1 = tanhf(z1);
                float nrm = fmaxf(sqrtf(t0 * t0 + t1 * t1), 1e-12f);
                wav0 *= (xs0 > 0.0f ? t0 : t1) / nrm;
            }
            // sample 1 of this group
            {
                const float z0 = fmaf(-2.0f, S01, C0);
                const float z1 = fmaf(-2.0f, S11, C1);
                const float t0 = tanhf(z0), t1 = tanhf(z1);
                float nrm = fmaxf(sqrtf(t0 * t0 + t1 * t1), 1e-12f);
                wav1 *= (xs1 > 0.0f ? t0 : t1) / nrm;
            }
        }
        buf ^= 1;
    }

    if (leader) {
        out[n0 + sl0] = wav0;
        out[n0 + sl1] = wav1;
    }
}

extern "C" void kernel_launch(void* const* d_in, const int* in_sizes, int n_in,
                              void* d_out, int out_size) {
    const float* x  = (const float*)d_in[0];
    const float* W1 = (const float*)d_in[1];
    const float* b1 = (const float*)d_in[2];
    const float* W2 = (const float*)d_in[3];
    const float* b2 = (const float*)d_in[4];
    float* out = (float*)d_out;

    const int smem_bytes =
        (4 * W1_FLOATS + B_SAMP * D_SITES) * (int)sizeof(float) + 32 * (int)sizeof(float4);

    cudaFuncSetAttribute(qnade_kernel,
                         cudaFuncAttributeMaxDynamicSharedMemorySize, smem_bytes);

    qnade_kernel<<<N_SAMP / B_SAMP, THREADS, smem_bytes>>>(x, W1, b1, W2, b2, out);
}